// round 4
// baseline (speedup 1.0000x reference)
#include <cuda_runtime.h>
#include <math.h>

#define Nn   50000
#define Ee   800000
#define Ff   32
#define NINVc 128
#define NLc  4
#define Hc   64
#define Gc   2048
#define EPSf 1e-6f

typedef unsigned long long u64;

// ---------------- device scratch (no allocs allowed) ----------------
__device__ float  g_edge_in[Ee*5];
__device__ float  g_u[Ee*3];
__device__ int    g_src[Ee];
__device__ int    g_dst[Ee];
__device__ float  g_s[Nn*Ff];
__device__ float  g_v[Nn*Ff*3];
__device__ float4 g_acc[Nn*Ff];       // {ms, mv0, mv1, mv2} accumulators
__device__ float  g_invden[Nn];
__device__ float  g_cnt[Nn];
__device__ float  g_xg[Gc*NINVc];
__device__ float  g_gcnt[Gc];
__device__ float  g_xgp[Gc*NINVc];
__device__ float  g_z1[Gc*NINVc];
__device__ float  g_mean1[NINVc], g_rstd1[NINVc], g_mean2[NINVc], g_rstd2[NINVc];

__device__ __forceinline__ float elu1(float x) { return x > 0.f ? x : expm1f(x); }
__device__ __forceinline__ float elu_fast(float x) { return x > 0.f ? x : (__expf(x) - 1.f); }

// f32x2 packed-math helpers (FFMA2 — only reachable via PTX)
__device__ __forceinline__ u64 pack2(float lo, float hi) {
    u64 r; asm("mov.b64 %0, {%1,%2};" : "=l"(r) : "f"(lo), "f"(hi)); return r;
}
__device__ __forceinline__ void unpack2(float& lo, float& hi, u64 v) {
    asm("mov.b64 {%0,%1}, %2;" : "=f"(lo), "=f"(hi) : "l"(v));
}
__device__ __forceinline__ u64 fma2(u64 a, u64 b, u64 c) {
    u64 d; asm("fma.rn.f32x2 %0, %1, %2, %3;" : "=l"(d) : "l"(a), "l"(b), "l"(c)); return d;
}
__device__ __forceinline__ u64 add2(u64 a, u64 b) {
    u64 d; asm("add.rn.f32x2 %0, %1, %2;" : "=l"(d) : "l"(a), "l"(b)); return d;
}

// ---------------- combined zero kernel (launch #1) ----------------
__global__ void k_zero_all() {
    int i = blockIdx.x*blockDim.x + threadIdx.x;
    if (i < Nn*Ff) { g_acc[i] = make_float4(0.f,0.f,0.f,0.f); return; }
    i -= Nn*Ff;
    if (i < Nn) { g_cnt[i] = 0.f; return; }
    i -= Nn;
    if (i < Gc) { g_gcnt[i] = 0.f; return; }
    i -= Gc;
    if (i < Gc*NINVc) g_xg[i] = 0.f;
}

// ---------------- preprocessing ----------------
__global__ void k_edge_prep(const float* __restrict__ pos,
                            const int* __restrict__ ei,
                            const float* __restrict__ eattr) {
    int e = blockIdx.x*blockDim.x + threadIdx.x;
    if (e >= Ee) return;
    int src = ei[e];
    int dst = ei[Ee + e];
    float dx = pos[dst*3+0] - pos[src*3+0];
    float dy = pos[dst*3+1] - pos[src*3+1];
    float dz = pos[dst*3+2] - pos[src*3+2];
    float d  = sqrtf(dx*dx + dy*dy + dz*dz + EPSf);
    float inv = 1.0f/d;
    g_edge_in[e*5+0] = d;
    g_edge_in[e*5+1] = eattr[e*4+0];
    g_edge_in[e*5+2] = eattr[e*4+1];
    g_edge_in[e*5+3] = eattr[e*4+2];
    g_edge_in[e*5+4] = eattr[e*4+3];
    g_u[e*3+0] = dx*inv;
    g_u[e*3+1] = dy*inv;
    g_u[e*3+2] = dz*inv;
    g_src[e] = src;
    g_dst[e] = dst;
    atomicAdd(&g_cnt[dst], 1.f);
}
__global__ void k_gcnt(const int* __restrict__ batch) {
    int n = blockIdx.x*blockDim.x + threadIdx.x;
    if (n < Nn) atomicAdd(&g_gcnt[batch[n]], 1.f);
}
__global__ void k_invden() {
    int n = blockIdx.x*blockDim.x + threadIdx.x;
    if (n < Nn) g_invden[n] = 1.f / fmaxf(g_cnt[n], 1.f);
}

// ---------------- embedding ----------------
__global__ void k_embed(const float* __restrict__ x, const float* __restrict__ pos,
                        const float* __restrict__ W_es, const float* __restrict__ b_es,
                        const float* __restrict__ W_ev) {
    int idx = blockIdx.x*blockDim.x + threadIdx.x;
    if (idx >= Nn*Ff) return;
    int n = idx >> 5, f = idx & 31;
    const float* xr = x + n*5;
    float s = b_es[f], ev = 0.f;
    #pragma unroll
    for (int k = 0; k < 5; k++) {
        float xv = xr[k];
        s  += xv * W_es[k*Ff + f];
        ev += xv * W_ev[k*Ff + f];
    }
    g_s[idx] = s;
    float p0 = pos[n*3+0], p1 = pos[n*3+1], p2 = pos[n*3+2];
    g_v[idx*3+0] = ev*p0;
    g_v[idx*3+1] = ev*p1;
    g_v[idx*3+2] = ev*p2;
}

// ---------------- per-layer fused: edge MLP (f32x2 GEMM, dup-weight smem) + message + scatter ----
// smem (floats, u64-aligned blocks first):
//   w2d[6144 u64 = 12288 fl] b2d[96 u64 = 192 fl] w1s[320] b1s[64]
//   eins[320] us[192] hT[64*64] srcs[64](int) dsts[64](int)
#define MSG_SMEM_FLOATS (12288+192+320+64+320+192+4096+64+64)
__global__ void __launch_bounds__(128, 3)
k_msg(const float* __restrict__ W1, const float* __restrict__ b1,
      const float* __restrict__ W2, const float* __restrict__ b2) {
    extern __shared__ float sm[];
    u64*   w2d  = (u64*)sm;                  // [k=64][f=96] duplicated weights
    u64*   b2d  = w2d + 6144;                // [96] duplicated bias
    float* w1s  = (float*)(b2d + 96);        // 5x64
    float* b1s  = w1s + 320;                 // 64
    float* eins = b1s + 64;                  // 64x5
    float* us   = eins + 320;                // 64x3
    float* hT   = us + 192;                  // [k=64][e=64]
    int*   srcs = (int*)(hT + 4096);         // 64
    int*   dsts = srcs + 64;                 // 64

    int tid = threadIdx.x;
    for (int i = tid; i < 320;  i += 128) w1s[i] = W1[i];
    for (int i = tid; i < 64;   i += 128) b1s[i] = b1[i];
    for (int i = tid; i < 6144; i += 128) { float w = W2[i]; w2d[i] = pack2(w, w); }
    for (int i = tid; i < 96;   i += 128) { float w = b2[i]; b2d[i] = pack2(w, w); }

    const int ntiles = Ee / 64;
    for (int tile = blockIdx.x; tile < ntiles; tile += gridDim.x) {
        __syncthreads();   // weight preload (1st iter) / shared reuse (later)
        int e0 = tile * 64;
        for (int i = tid; i < 320; i += 128) eins[i] = g_edge_in[e0*5 + i];
        for (int i = tid; i < 192; i += 128) us[i]   = g_u[e0*3 + i];
        if (tid < 64) { srcs[tid] = g_src[e0 + tid]; dsts[tid] = g_dst[e0 + tid]; }
        __syncthreads();

        // MLP1: hidden = elu(edge_in @ W1 + b1). thread = (e = tid&63, 32 j's as 16 f32x2 pairs)
        {
            int e  = tid & 63;
            int j0 = (tid >> 6) * 32;
            float x0 = eins[e*5+0], x1 = eins[e*5+1], x2 = eins[e*5+2];
            float x3 = eins[e*5+3], x4 = eins[e*5+4];
            u64 xd[5] = { pack2(x0,x0), pack2(x1,x1), pack2(x2,x2), pack2(x3,x3), pack2(x4,x4) };
            #pragma unroll
            for (int i = 0; i < 16; i++) {
                int j = j0 + 2*i;
                u64 a = *(const u64*)&b1s[j];
                #pragma unroll
                for (int k = 0; k < 5; k++)
                    a = fma2(xd[k], *(const u64*)&w1s[k*64 + j], a);
                float lo, hi; unpack2(lo, hi, a);
                hT[j*64 + e]     = elu_fast(lo);
                hT[(j+1)*64 + e] = elu_fast(hi);
            }
        }
        __syncthreads();

        // GEMM2: pairs over EDGES (LDS.64 acts, no dup MOVs), dup weights from smem.
        // thread: og = tid&15 (f base), eg = tid>>4 -> edges [eg*8, eg*8+8) as 4 pairs.
        // outputs jj: 0,1 -> gs f={og,og+16}; 2,3 -> gv; 4,5 -> gsv.
        {
            int og = tid & 15;
            int eg = tid >> 4;
            int ebase = eg * 8;
            int cmap0 = og, cmap1 = og + 16;
            u64 acc2[4][6];
            #pragma unroll
            for (int p = 0; p < 4; p++)
                #pragma unroll
                for (int jj = 0; jj < 6; jj++) acc2[p][jj] = 0ull;
            #pragma unroll 2
            for (int k = 0; k < 64; k++) {
                const float* hrow = &hT[k*64 + ebase];
                u64 a0 = *(const u64*)&hrow[0];
                u64 a1 = *(const u64*)&hrow[2];
                u64 a2 = *(const u64*)&hrow[4];
                u64 a3 = *(const u64*)&hrow[6];
                const u64* wr = &w2d[k*96];
                u64 w0 = wr[cmap0],      w1v = wr[cmap1];
                u64 w2v = wr[32+cmap0],  w3 = wr[32+cmap1];
                u64 w4 = wr[64+cmap0],   w5 = wr[64+cmap1];
                acc2[0][0]=fma2(a0,w0,acc2[0][0]); acc2[0][1]=fma2(a0,w1v,acc2[0][1]);
                acc2[0][2]=fma2(a0,w2v,acc2[0][2]); acc2[0][3]=fma2(a0,w3,acc2[0][3]);
                acc2[0][4]=fma2(a0,w4,acc2[0][4]); acc2[0][5]=fma2(a0,w5,acc2[0][5]);
                acc2[1][0]=fma2(a1,w0,acc2[1][0]); acc2[1][1]=fma2(a1,w1v,acc2[1][1]);
                acc2[1][2]=fma2(a1,w2v,acc2[1][2]); acc2[1][3]=fma2(a1,w3,acc2[1][3]);
                acc2[1][4]=fma2(a1,w4,acc2[1][4]); acc2[1][5]=fma2(a1,w5,acc2[1][5]);
                acc2[2][0]=fma2(a2,w0,acc2[2][0]); acc2[2][1]=fma2(a2,w1v,acc2[2][1]);
                acc2[2][2]=fma2(a2,w2v,acc2[2][2]); acc2[2][3]=fma2(a2,w3,acc2[2][3]);
                acc2[2][4]=fma2(a2,w4,acc2[2][4]); acc2[2][5]=fma2(a2,w5,acc2[2][5]);
                acc2[3][0]=fma2(a3,w0,acc2[3][0]); acc2[3][1]=fma2(a3,w1v,acc2[3][1]);
                acc2[3][2]=fma2(a3,w2v,acc2[3][2]); acc2[3][3]=fma2(a3,w3,acc2[3][3]);
                acc2[3][4]=fma2(a3,w4,acc2[3][4]); acc2[3][5]=fma2(a3,w5,acc2[3][5]);
            }
            u64 bb[6] = { b2d[cmap0], b2d[cmap1], b2d[32+cmap0], b2d[32+cmap1],
                          b2d[64+cmap0], b2d[64+cmap1] };
            #pragma unroll
            for (int p = 0; p < 4; p++) {
                float gsv2[6], gsv2h[6];
                #pragma unroll
                for (int jj = 0; jj < 6; jj++)
                    unpack2(gsv2[jj], gsv2h[jj], add2(acc2[p][jj], bb[jj]));
                // two edges in this pair
                #pragma unroll
                for (int half = 0; half < 2; half++) {
                    int e = ebase + 2*p + half;
                    float gs0 = half ? gsv2h[0] : gsv2[0];
                    float gs1 = half ? gsv2h[1] : gsv2[1];
                    float gv0 = half ? gsv2h[2] : gsv2[2];
                    float gv1 = half ? gsv2h[3] : gsv2[3];
                    float gt0 = half ? gsv2h[4] : gsv2[4];
                    float gt1 = half ? gsv2h[5] : gsv2[5];
                    int src = srcs[e], dst = dsts[e];
                    float u0 = us[e*3+0], u1 = us[e*3+1], u2 = us[e*3+2];
                    // f = og
                    {
                        float ssrc = g_s[src*Ff + og];
                        const float* vp = &g_v[(src*Ff + og)*3];
                        float t = gt0 * ssrc;
                        float4 m = make_float4(gs0*ssrc,
                                               gv0*vp[0] + t*u0,
                                               gv0*vp[1] + t*u1,
                                               gv0*vp[2] + t*u2);
                        atomicAdd(&g_acc[dst*Ff + og], m);     // RED.128
                    }
                    // f = og + 16
                    {
                        float ssrc = g_s[src*Ff + og + 16];
                        const float* vp = &g_v[(src*Ff + og + 16)*3];
                        float t = gt1 * ssrc;
                        float4 m = make_float4(gs1*ssrc,
                                               gv1*vp[0] + t*u0,
                                               gv1*vp[1] + t*u1,
                                               gv1*vp[2] + t*u2);
                        atomicAdd(&g_acc[dst*Ff + og + 16], m);
                    }
                }
            }
        }
    }
}

// ---------------- per-layer node update: residual s,v + acc reset ----------------
__global__ void k_update(const float* __restrict__ Ws, const float* __restrict__ Wv) {
    __shared__ float  wss[1024], wvs[1024];
    __shared__ float4 msh[4][32];
    int tid = threadIdx.x;
    for (int i = tid; i < 1024; i += 128) { wss[i] = Ws[i]; wvs[i] = Wv[i]; }
    __syncthreads();
    int w = tid >> 5, lane = tid & 31;
    int node = blockIdx.x*4 + w;
    if (node >= Nn) return;
    float invd = g_invden[node];
    float4 a = g_acc[node*Ff + lane];
    g_acc[node*Ff + lane] = make_float4(0.f,0.f,0.f,0.f);  // reset for next layer
    msh[w][lane] = make_float4(a.x*invd, a.y*invd, a.z*invd, a.w*invd);
    __syncwarp();
    float so = 0.f, v0 = 0.f, v1 = 0.f, v2 = 0.f;
    #pragma unroll
    for (int f = 0; f < 32; f++) {
        float4 m = msh[w][f];
        float wsv = wss[f*32 + lane];
        float wvv = wvs[f*32 + lane];
        so += m.x*wsv;
        v0 += m.y*wvv; v1 += m.z*wvv; v2 += m.w*wvv;
    }
    g_s[node*Ff + lane] += elu1(so);
    float* vp = &g_v[(node*Ff + lane)*3];
    vp[0] += v0; vp[1] += v1; vp[2] += v2;
}

// ---------------- invariant map + graph pooling (atomic) ----------------
__global__ void k_inv(const float* __restrict__ W_inv, const float* __restrict__ b_inv,
                      const int* __restrict__ batch) {
    __shared__ float wi[64*128];
    __shared__ float bi[128];
    __shared__ float feat[4][64];
    int tid = threadIdx.x;
    for (int i = tid; i < 64*128; i += 128) wi[i] = W_inv[i];
    if (tid < 128) bi[tid] = b_inv[tid];
    __syncthreads();
    int w = tid >> 5, lane = tid & 31;
    int nwarps = gridDim.x*4;
    for (int node = blockIdx.x*4 + w; node < Nn; node += nwarps) {
        float sval = g_s[node*Ff + lane];
        const float* vp = &g_v[(node*Ff + lane)*3];
        float vn = sqrtf(vp[0]*vp[0] + vp[1]*vp[1] + vp[2]*vp[2] + EPSf);
        feat[w][lane]      = sval;
        feat[w][32 + lane] = vn;
        __syncwarp();
        int b = batch[node];
        #pragma unroll
        for (int r = 0; r < 4; r++) {
            int c = lane + 32*r;
            float acc = bi[c];
            #pragma unroll 8
            for (int k = 0; k < 64; k++) acc += feat[w][k] * wi[k*128 + c];
            atomicAdd(&g_xg[b*NINVc + c], acc);
        }
        __syncwarp();
    }
}

// ---------------- head ----------------
__global__ void k_pool_bn1() {
    __shared__ float ssum[256], ssq[256];
    int c = blockIdx.x, tid = threadIdx.x;
    float s = 0.f, q = 0.f;
    for (int g = tid; g < Gc; g += 256) {
        float val = g_xg[g*NINVc + c] / fmaxf(g_gcnt[g], 1.f);
        g_xgp[g*NINVc + c] = val;
        s += val; q += val*val;
    }
    ssum[tid] = s; ssq[tid] = q; __syncthreads();
    for (int st = 128; st > 0; st >>= 1) {
        if (tid < st) { ssum[tid] += ssum[tid+st]; ssq[tid] += ssq[tid+st]; }
        __syncthreads();
    }
    if (tid == 0) {
        float m = ssum[0] / (float)Gc;
        float var = ssq[0] / (float)Gc - m*m;
        g_mean1[c] = m;
        g_rstd1[c] = rsqrtf(var + 1e-5f);
    }
}
__global__ void k_fc1(const float* __restrict__ g1, const float* __restrict__ be1,
                      const float* __restrict__ Wf1, const float* __restrict__ bf1) {
    __shared__ float a[128];
    int g = blockIdx.x, j = threadIdx.x;
    float xv = g_xgp[g*NINVc + j];
    a[j] = elu1((xv - g_mean1[j]) * g_rstd1[j] * g1[j] + be1[j]);
    __syncthreads();
    float acc = bf1[j];
    #pragma unroll 8
    for (int k = 0; k < 128; k++) acc += a[k] * Wf1[k*128 + j];
    g_z1[g*NINVc + j] = acc;
}
__global__ void k_bn2() {
    __shared__ float ssum[256], ssq[256];
    int c = blockIdx.x, tid = threadIdx.x;
    float s = 0.f, q = 0.f;
    for (int g = tid; g < Gc; g += 256) {
        float val = g_z1[g*NINVc + c];
        s += val; q += val*val;
    }
    ssum[tid] = s; ssq[tid] = q; __syncthreads();
    for (int st = 128; st > 0; st >>= 1) {
        if (tid < st) { ssum[tid] += ssum[tid+st]; ssq[tid] += ssq[tid+st]; }
        __syncthreads();
    }
    if (tid == 0) {
        float m = ssum[0] / (float)Gc;
        float var = ssq[0] / (float)Gc - m*m;
        g_mean2[c] = m;
        g_rstd2[c] = rsqrtf(var + 1e-5f);
    }
}
__global__ void k_head(const float* __restrict__ g2, const float* __restrict__ be2,
                       const float* __restrict__ Wf2, const float* __restrict__ bf2,
                       float* __restrict__ out) {
    int w = threadIdx.x >> 5, lane = threadIdx.x & 31;
    int g = blockIdx.x*4 + w;
    if (g >= Gc) return;
    float p = 0.f;
    for (int k = lane; k < 128; k += 32) {
        float zv = g_z1[g*NINVc + k];
        float av = elu1((zv - g_mean2[k]) * g_rstd2[k] * g2[k] + be2[k]);
        p += av * Wf2[k];
    }
    #pragma unroll
    for (int off = 16; off; off >>= 1) p += __shfl_down_sync(0xffffffffu, p, off);
    if (lane == 0) out[g] = p + bf2[0];
}

// ---------------- launch ----------------
extern "C" void kernel_launch(void* const* d_in, const int* in_sizes, int n_in,
                              void* d_out, int out_size) {
    const float* x     = (const float*)d_in[0];
    const float* pos   = (const float*)d_in[1];
    const int*   ei    = (const int*)d_in[2];     // int32 (JAX x64 disabled)
    const float* eattr = (const float*)d_in[3];
    const int*   batch = (const int*)d_in[4];     // int32
    const float* W_es  = (const float*)d_in[5];
    const float* b_es  = (const float*)d_in[6];
    const float* W_ev  = (const float*)d_in[7];
    const float* W1    = (const float*)d_in[8];
    const float* b1    = (const float*)d_in[9];
    const float* W2    = (const float*)d_in[10];
    const float* b2    = (const float*)d_in[11];
    const float* Ws    = (const float*)d_in[12];
    const float* Wv    = (const float*)d_in[13];
    const float* W_inv = (const float*)d_in[14];
    const float* b_inv = (const float*)d_in[15];
    const float* g1    = (const float*)d_in[16];
    const float* be1   = (const float*)d_in[17];
    const float* Wf1   = (const float*)d_in[18];
    const float* bf1   = (const float*)d_in[19];
    const float* g2    = (const float*)d_in[20];
    const float* be2   = (const float*)d_in[21];
    const float* Wf2   = (const float*)d_in[22];
    const float* bf2   = (const float*)d_in[23];
    float* out = (float*)d_out;

    const int MSG_SMEM = MSG_SMEM_FLOATS * 4;
    cudaFuncSetAttribute(k_msg, cudaFuncAttributeMaxDynamicSharedMemorySize, MSG_SMEM);

    int ztotal = Nn*Ff + Nn + Gc + Gc*NINVc;
    k_zero_all<<<(ztotal + 255)/256, 256>>>();                       // #1
    k_edge_prep<<<(Ee + 255)/256, 256>>>(pos, ei, eattr);            // #2
    k_embed<<<(Nn*Ff + 255)/256, 256>>>(x, pos, W_es, b_es, W_ev);   // #3

    // layer 0 k_msg is my launch #4 -> ncu -s 5 -c 1 captures it
    k_msg<<<2048, 128, MSG_SMEM>>>(W1, b1, W2, b2);                  // #4
    k_invden<<<(Nn + 255)/256, 256>>>();                             // #5 (before 1st update)
    k_update<<<Nn/4, 128>>>(Ws, Wv);                                 // #6

    for (int l = 1; l < NLc; l++) {
        k_msg<<<2048, 128, MSG_SMEM>>>(W1 + l*5*Hc, b1 + l*Hc,
                                       W2 + l*Hc*3*Ff, b2 + l*3*Ff);
        k_update<<<Nn/4, 128>>>(Ws + l*Ff*Ff, Wv + l*Ff*Ff);
    }

    k_gcnt<<<(Nn + 255)/256, 256>>>(batch);
    k_inv<<<1024, 128>>>(W_inv, b_inv, batch);
    k_pool_bn1<<<NINVc, 256>>>();
    k_fc1<<<Gc, 128>>>(g1, be1, Wf1, bf1);
    k_bn2<<<NINVc, 256>>>();
    k_head<<<Gc/4, 128>>>(g2, be2, Wf2, bf2, out);
}

// round 7
// speedup vs baseline: 1.3263x; 1.3263x over previous
#include <cuda_runtime.h>
#include <cuda_bf16.h>
#include <math.h>
#include <cstdint>

#define Nn   50000
#define Ee   800000
#define Ff   32
#define NINVc 128
#define NLc  4
#define Hc   64
#define Gc   2048
#define EPSf 1e-6f
#define NT   (Ee/128)   // 6250 tiles of 128 edges

// ---------------- device scratch (no allocs allowed) ----------------
__device__ __align__(16) float  g_edge_in[Ee*5];
__device__ float  g_u[Ee*3];
__device__ int    g_src[Ee];
__device__ int    g_dst[Ee];
__device__ __align__(16) float  g_s[Nn*Ff];
__device__ __align__(16) float  g_v0[Nn*Ff];
__device__ __align__(16) float  g_v1[Nn*Ff];
__device__ __align__(16) float  g_v2[Nn*Ff];
__device__ float4 g_acc[Nn*Ff];       // {ms, mv0, mv1, mv2}
__device__ float  g_invden[Nn];
__device__ float  g_cnt[Nn];
__device__ float  g_xg[Gc*NINVc];
__device__ float  g_gcnt[Gc];
__device__ float  g_xgp[Gc*NINVc];
__device__ float  g_z1[Gc*NINVc];
__device__ float  g_mean1[NINVc], g_rstd1[NINVc], g_mean2[NINVc], g_rstd2[NINVc];

__device__ __forceinline__ float elu1(float x) { return x > 0.f ? x : expm1f(x); }
__device__ __forceinline__ float elu_fast(float x) { return x > 0.f ? x : (__expf(x) - 1.f); }

// warp-level bf16 mma (sm_80+ baseline PTX; works on plain sm_103 target)
__device__ __forceinline__ void mma16816(float* d, const uint32_t* a, const uint32_t* b) {
    asm volatile(
        "mma.sync.aligned.m16n8k16.row.col.f32.bf16.bf16.f32 "
        "{%0,%1,%2,%3}, {%4,%5,%6,%7}, {%8,%9}, {%0,%1,%2,%3};"
        : "+f"(d[0]), "+f"(d[1]), "+f"(d[2]), "+f"(d[3])
        : "r"(a[0]), "r"(a[1]), "r"(a[2]), "r"(a[3]), "r"(b[0]), "r"(b[1]));
}
__device__ __forceinline__ void bf16split(float x, uint16_t& h, uint16_t& l) {
    __nv_bfloat16 hb = __float2bfloat16_rn(x);
    float r = x - __bfloat162float(hb);
    __nv_bfloat16 lb = __float2bfloat16_rn(r);
    h = __bfloat16_as_ushort(hb);
    l = __bfloat16_as_ushort(lb);
}

// ---------------- zero / preprocessing ----------------
__global__ void k_zero_all() {
    int i = blockIdx.x*blockDim.x + threadIdx.x;
    if (i < Nn*Ff) { g_acc[i] = make_float4(0.f,0.f,0.f,0.f); return; }
    i -= Nn*Ff;
    if (i < Nn) { g_cnt[i] = 0.f; return; }
    i -= Nn;
    if (i < Gc) { g_gcnt[i] = 0.f; return; }
    i -= Gc;
    if (i < Gc*NINVc) g_xg[i] = 0.f;
}
__global__ void k_edge_prep(const float* __restrict__ pos,
                            const int* __restrict__ ei,
                            const float* __restrict__ eattr) {
    int e = blockIdx.x*blockDim.x + threadIdx.x;
    if (e >= Ee) return;
    int src = ei[e];
    int dst = ei[Ee + e];
    float dx = pos[dst*3+0] - pos[src*3+0];
    float dy = pos[dst*3+1] - pos[src*3+1];
    float dz = pos[dst*3+2] - pos[src*3+2];
    float d  = sqrtf(dx*dx + dy*dy + dz*dz + EPSf);
    float inv = 1.0f/d;
    g_edge_in[e*5+0] = d;
    g_edge_in[e*5+1] = eattr[e*4+0];
    g_edge_in[e*5+2] = eattr[e*4+1];
    g_edge_in[e*5+3] = eattr[e*4+2];
    g_edge_in[e*5+4] = eattr[e*4+3];
    g_u[e*3+0] = dx*inv;
    g_u[e*3+1] = dy*inv;
    g_u[e*3+2] = dz*inv;
    g_src[e] = src;
    g_dst[e] = dst;
    atomicAdd(&g_cnt[dst], 1.f);
}
__global__ void k_gcnt(const int* __restrict__ batch) {
    int n = blockIdx.x*blockDim.x + threadIdx.x;
    if (n < Nn) atomicAdd(&g_gcnt[batch[n]], 1.f);
}
__global__ void k_invden() {
    int n = blockIdx.x*blockDim.x + threadIdx.x;
    if (n < Nn) g_invden[n] = 1.f / fmaxf(g_cnt[n], 1.f);
}
__global__ void k_embed(const float* __restrict__ x, const float* __restrict__ pos,
                        const float* __restrict__ W_es, const float* __restrict__ b_es,
                        const float* __restrict__ W_ev) {
    int idx = blockIdx.x*blockDim.x + threadIdx.x;
    if (idx >= Nn*Ff) return;
    int n = idx >> 5, f = idx & 31;
    const float* xr = x + n*5;
    float s = b_es[f], ev = 0.f;
    #pragma unroll
    for (int k = 0; k < 5; k++) {
        float xv = xr[k];
        s  += xv * W_es[k*Ff + f];
        ev += xv * W_ev[k*Ff + f];
    }
    g_s[idx] = s;
    float p0 = pos[n*3+0], p1 = pos[n*3+1], p2 = pos[n*3+2];
    g_v0[idx] = ev*p0;
    g_v1[idx] = ev*p1;
    g_v2[idx] = ev*p2;
}

// ---------------- HMMA fused message kernel ----------------
// Tile = 128 edges, 256 threads (8 warps). Warp w owns edges [w*16, w*16+16).
// A (hidden acts, bf16 hi/lo) [128][72 pad], B (W2^T, bf16 hi/lo) [96][72 pad].
// 3-pass split mma: Ah*Bh + Ah*Bl + Al*Bh, fp32 acc (bias pre-loaded).
// Epilogue: each lane owns (edge, f-pair) triples directly from D fragments.
#define OFF_BH  0
#define OFF_BL  13824
#define OFF_AH  27648
#define OFF_AL  46080
#define OFF_W1S 64512
#define OFF_B1S 65792
#define OFF_B2S 66048
#define OFF_US  66432
#define OFF_SRC 67968
#define OFF_DST 68480
#define TC_SMEM 68992
__global__ void __launch_bounds__(256, 2)
k_msg_mma(const float* __restrict__ W1, const float* __restrict__ b1,
          const float* __restrict__ W2, const float* __restrict__ b2) {
    extern __shared__ char smc[];
    uint16_t* BH = (uint16_t*)(smc + OFF_BH);
    uint16_t* BL = (uint16_t*)(smc + OFF_BL);
    float* w1s = (float*)(smc + OFF_W1S);
    float* b1s = (float*)(smc + OFF_B1S);
    float* b2s = (float*)(smc + OFF_B2S);
    float* us  = (float*)(smc + OFF_US);
    int* srcs  = (int*)(smc + OFF_SRC);
    int* dsts  = (int*)(smc + OFF_DST);
    const uint32_t* AH32 = (const uint32_t*)(smc + OFF_AH);
    const uint32_t* AL32 = (const uint32_t*)(smc + OFF_AL);
    const uint32_t* BH32 = (const uint32_t*)(smc + OFF_BH);
    const uint32_t* BL32 = (const uint32_t*)(smc + OFF_BL);

    int tid = threadIdx.x;
    // stage weights once per block
    for (int i = tid; i < 320; i += 256) w1s[i] = W1[i];
    for (int i = tid; i < 64;  i += 256) b1s[i] = b1[i];
    for (int i = tid; i < 96;  i += 256) b2s[i] = b2[i];
    for (int idx = tid; idx < 96*64; idx += 256) {
        int n = idx >> 6, k = idx & 63;
        uint16_t h, l; bf16split(W2[k*96 + n], h, l);
        BH[n*72 + k] = h;
        BL[n*72 + k] = l;
    }

    int lane = tid & 31, warp = tid >> 5;
    int m0 = warp * 16;
    int r = lane >> 2, q = lane & 3;

    for (int tile = blockIdx.x; tile < NT; tile += gridDim.x) {
        __syncthreads();   // prior tile's smem reads done (and weight staging on 1st iter)
        int e0 = tile * 128;

        // --- MLP1 + bf16 split into A smem; stage edge meta ---
        {
            int e = tid >> 1;
            int jh = (tid & 1) * 32;
            const float* ein = &g_edge_in[(e0 + e)*5];
            float x0 = ein[0], x1 = ein[1], x2 = ein[2], x3 = ein[3], x4 = ein[4];
            uint32_t* AHw = (uint32_t*)(smc + OFF_AH) + e*36 + (jh >> 1);
            uint32_t* ALw = (uint32_t*)(smc + OFF_AL) + e*36 + (jh >> 1);
            #pragma unroll
            for (int i = 0; i < 16; i++) {
                int j = jh + 2*i;
                float2 bb = *(const float2*)&b1s[j];
                float a0 = bb.x, a1 = bb.y;
                float2 w;
                w = *(const float2*)&w1s[0*64 + j]; a0 = fmaf(x0, w.x, a0); a1 = fmaf(x0, w.y, a1);
                w = *(const float2*)&w1s[1*64 + j]; a0 = fmaf(x1, w.x, a0); a1 = fmaf(x1, w.y, a1);
                w = *(const float2*)&w1s[2*64 + j]; a0 = fmaf(x2, w.x, a0); a1 = fmaf(x2, w.y, a1);
                w = *(const float2*)&w1s[3*64 + j]; a0 = fmaf(x3, w.x, a0); a1 = fmaf(x3, w.y, a1);
                w = *(const float2*)&w1s[4*64 + j]; a0 = fmaf(x4, w.x, a0); a1 = fmaf(x4, w.y, a1);
                a0 = elu_fast(a0); a1 = elu_fast(a1);
                uint16_t h0,l0,h1,l1;
                bf16split(a0, h0, l0); bf16split(a1, h1, l1);
                AHw[i] = ((uint32_t)h1 << 16) | h0;
                ALw[i] = ((uint32_t)l1 << 16) | l0;
            }
            if (tid < 128) { srcs[tid] = g_src[e0 + tid]; dsts[tid] = g_dst[e0 + tid]; }
            for (int i = tid; i < 384; i += 256) us[i] = g_u[e0*3 + i];
        }
        __syncthreads();

        // --- GEMM2 via 3-pass split HMMA, bias preloaded ---
        float acc[12][4];
        #pragma unroll
        for (int nt = 0; nt < 12; nt++) {
            float2 bb = *(const float2*)&b2s[nt*8 + q*2];
            acc[nt][0] = bb.x; acc[nt][1] = bb.y;
            acc[nt][2] = bb.x; acc[nt][3] = bb.y;
        }
        #pragma unroll
        for (int ks = 0; ks < 4; ks++) {
            int k2 = ks*8 + q;
            int ra = (m0 + r)*36 + k2;
            int rb = (m0 + r + 8)*36 + k2;
            uint32_t ah[4], al[4];
            ah[0] = AH32[ra]; ah[1] = AH32[rb]; ah[2] = AH32[ra+4]; ah[3] = AH32[rb+4];
            al[0] = AL32[ra]; al[1] = AL32[rb]; al[2] = AL32[ra+4]; al[3] = AL32[rb+4];
            #pragma unroll
            for (int nt = 0; nt < 12; nt++) {
                int bi = (nt*8 + r)*36 + k2;
                uint32_t bh[2] = { BH32[bi], BH32[bi+4] };
                uint32_t bl[2] = { BL32[bi], BL32[bi+4] };
                mma16816(acc[nt], ah, bh);
                mma16816(acc[nt], ah, bl);
                mma16816(acc[nt], al, bh);
            }
        }

        // --- epilogue: messages + RED.128 scatter from fragments ---
        #pragma unroll
        for (int half = 0; half < 2; half++) {
            int e = m0 + r + half*8;
            int src = srcs[e], dst = dsts[e];
            float u0 = us[e*3+0], u1 = us[e*3+1], u2 = us[e*3+2];
            const float* srow = g_s + src*Ff;
            const float* p0r = g_v0 + src*Ff;
            const float* p1r = g_v1 + src*Ff;
            const float* p2r = g_v2 + src*Ff;
            float4* arow = g_acc + dst*Ff;
            #pragma unroll
            for (int nt = 0; nt < 4; nt++) {
                int f = nt*8 + q*2;
                float gs0 = acc[nt  ][half*2+0], gs1 = acc[nt  ][half*2+1];
                float gv0 = acc[nt+4][half*2+0], gv1 = acc[nt+4][half*2+1];
                float gt0 = acc[nt+8][half*2+0], gt1 = acc[nt+8][half*2+1];
                float2 ss = *(const float2*)&srow[f];
                float2 p0 = *(const float2*)&p0r[f];
                float2 p1 = *(const float2*)&p1r[f];
                float2 p2 = *(const float2*)&p2r[f];
                float t0 = gt0*ss.x, t1 = gt1*ss.y;
                atomicAdd(&arow[f],
                    make_float4(gs0*ss.x, fmaf(gv0, p0.x, t0*u0),
                                fmaf(gv0, p1.x, t0*u1), fmaf(gv0, p2.x, t0*u2)));
                atomicAdd(&arow[f+1],
                    make_float4(gs1*ss.y, fmaf(gv1, p0.y, t1*u0),
                                fmaf(gv1, p1.y, t1*u1), fmaf(gv1, p2.y, t1*u2)));
            }
        }
    }
}

// ---------------- per-layer node update: residual s,v + acc reset ----------------
__global__ void k_update(const float* __restrict__ Ws, const float* __restrict__ Wv) {
    __shared__ float  wss[1024], wvs[1024];
    __shared__ float4 msh[4][32];
    int tid = threadIdx.x;
    for (int i = tid; i < 1024; i += 128) { wss[i] = Ws[i]; wvs[i] = Wv[i]; }
    __syncthreads();
    int w = tid >> 5, lane = tid & 31;
    int node = blockIdx.x*4 + w;
    if (node >= Nn) return;
    float invd = g_invden[node];
    float4 a = g_acc[node*Ff + lane];
    g_acc[node*Ff + lane] = make_float4(0.f,0.f,0.f,0.f);  // reset for next layer
    msh[w][lane] = make_float4(a.x*invd, a.y*invd, a.z*invd, a.w*invd);
    __syncwarp();
    float so = 0.f, v0 = 0.f, v1 = 0.f, v2 = 0.f;
    #pragma unroll
    for (int f = 0; f < 32; f++) {
        float4 m = msh[w][f];
        float wsv = wss[f*32 + lane];
        float wvv = wvs[f*32 + lane];
        so += m.x*wsv;
        v0 += m.y*wvv; v1 += m.z*wvv; v2 += m.w*wvv;
    }
    int i = node*Ff + lane;
    g_s[i] += elu1(so);
    g_v0[i] += v0; g_v1[i] += v1; g_v2[i] += v2;
}

// ---------------- invariant map + graph pooling (atomic) ----------------
__global__ void k_inv(const float* __restrict__ W_inv, const float* __restrict__ b_inv,
                      const int* __restrict__ batch) {
    __shared__ float wi[64*128];
    __shared__ float bi[128];
    __shared__ float feat[4][64];
    int tid = threadIdx.x;
    for (int i = tid; i < 64*128; i += 128) wi[i] = W_inv[i];
    if (tid < 128) bi[tid] = b_inv[tid];
    __syncthreads();
    int w = tid >> 5, lane = tid & 31;
    int nwarps = gridDim.x*4;
    for (int node = blockIdx.x*4 + w; node < Nn; node += nwarps) {
        int i = node*Ff + lane;
        float sval = g_s[i];
        float a0 = g_v0[i], a1 = g_v1[i], a2 = g_v2[i];
        float vn = sqrtf(a0*a0 + a1*a1 + a2*a2 + EPSf);
        feat[w][lane]      = sval;
        feat[w][32 + lane] = vn;
        __syncwarp();
        int b = batch[node];
        #pragma unroll
        for (int rr = 0; rr < 4; rr++) {
            int c = lane + 32*rr;
            float acc = bi[c];
            #pragma unroll 8
            for (int k = 0; k < 64; k++) acc += feat[w][k] * wi[k*128 + c];
            atomicAdd(&g_xg[b*NINVc + c], acc);
        }
        __syncwarp();
    }
}

// ---------------- head ----------------
__global__ void k_pool_bn1() {
    __shared__ float ssum[256], ssq[256];
    int c = blockIdx.x, tid = threadIdx.x;
    float s = 0.f, q = 0.f;
    for (int g = tid; g < Gc; g += 256) {
        float val = g_xg[g*NINVc + c] / fmaxf(g_gcnt[g], 1.f);
        g_xgp[g*NINVc + c] = val;
        s += val; q += val*val;
    }
    ssum[tid] = s; ssq[tid] = q; __syncthreads();
    for (int st = 128; st > 0; st >>= 1) {
        if (tid < st) { ssum[tid] += ssum[tid+st]; ssq[tid] += ssq[tid+st]; }
        __syncthreads();
    }
    if (tid == 0) {
        float m = ssum[0] / (float)Gc;
        float var = ssq[0] / (float)Gc - m*m;
        g_mean1[c] = m;
        g_rstd1[c] = rsqrtf(var + 1e-5f);
    }
}
__global__ void k_fc1(const float* __restrict__ g1, const float* __restrict__ be1,
                      const float* __restrict__ Wf1, const float* __restrict__ bf1) {
    __shared__ float a[128];
    int g = blockIdx.x, j = threadIdx.x;
    float xv = g_xgp[g*NINVc + j];
    a[j] = elu1((xv - g_mean1[j]) * g_rstd1[j] * g1[j] + be1[j]);
    __syncthreads();
    float acc = bf1[j];
    #pragma unroll 8
    for (int k = 0; k < 128; k++) acc += a[k] * Wf1[k*128 + j];
    g_z1[g*NINVc + j] = acc;
}
__global__ void k_bn2() {
    __shared__ float ssum[256], ssq[256];
    int c = blockIdx.x, tid = threadIdx.x;
    float s = 0.f, q = 0.f;
    for (int g = tid; g < Gc; g += 256) {
        float val = g_z1[g*NINVc + c];
        s += val; q += val*val;
    }
    ssum[tid] = s; ssq[tid] = q; __syncthreads();
    for (int st = 128; st > 0; st >>= 1) {
        if (tid < st) { ssum[tid] += ssum[tid+st]; ssq[tid] += ssq[tid+st]; }
        __syncthreads();
    }
    if (tid == 0) {
        float m = ssum[0] / (float)Gc;
        float var = ssq[0] / (float)Gc - m*m;
        g_mean2[c] = m;
        g_rstd2[c] = rsqrtf(var + 1e-5f);
    }
}
__global__ void k_head(const float* __restrict__ g2, const float* __restrict__ be2,
                       const float* __restrict__ Wf2, const float* __restrict__ bf2,
                       float* __restrict__ out) {
    int w = threadIdx.x >> 5, lane = threadIdx.x & 31;
    int g = blockIdx.x*4 + w;
    if (g >= Gc) return;
    float p = 0.f;
    for (int k = lane; k < 128; k += 32) {
        float zv = g_z1[g*NINVc + k];
        float av = elu1((zv - g_mean2[k]) * g_rstd2[k] * g2[k] + be2[k]);
        p += av * Wf2[k];
    }
    #pragma unroll
    for (int off = 16; off; off >>= 1) p += __shfl_down_sync(0xffffffffu, p, off);
    if (lane == 0) out[g] = p + bf2[0];
}

// ---------------- launch ----------------
extern "C" void kernel_launch(void* const* d_in, const int* in_sizes, int n_in,
                              void* d_out, int out_size) {
    const float* x     = (const float*)d_in[0];
    const float* pos   = (const float*)d_in[1];
    const int*   ei    = (const int*)d_in[2];     // int32 (JAX x64 disabled)
    const float* eattr = (const float*)d_in[3];
    const int*   batch = (const int*)d_in[4];     // int32
    const float* W_es  = (const float*)d_in[5];
    const float* b_es  = (const float*)d_in[6];
    const float* W_ev  = (const float*)d_in[7];
    const float* W1    = (const float*)d_in[8];
    const float* b1    = (const float*)d_in[9];
    const float* W2    = (const float*)d_in[10];
    const float* b2    = (const float*)d_in[11];
    const float* Ws    = (const float*)d_in[12];
    const float* Wv    = (const float*)d_in[13];
    const float* W_inv = (const float*)d_in[14];
    const float* b_inv = (const float*)d_in[15];
    const float* g1    = (const float*)d_in[16];
    const float* be1   = (const float*)d_in[17];
    const float* Wf1   = (const float*)d_in[18];
    const float* bf1   = (const float*)d_in[19];
    const float* g2    = (const float*)d_in[20];
    const float* be2   = (const float*)d_in[21];
    const float* Wf2   = (const float*)d_in[22];
    const float* bf2   = (const float*)d_in[23];
    float* out = (float*)d_out;

    cudaFuncSetAttribute(k_msg_mma, cudaFuncAttributeMaxDynamicSharedMemorySize, TC_SMEM);

    int ztotal = Nn*Ff + Nn + Gc + Gc*NINVc;
    k_zero_all<<<(ztotal + 255)/256, 256>>>();                       // #1
    k_edge_prep<<<(Ee + 255)/256, 256>>>(pos, ei, eattr);            // #2
    k_embed<<<(Nn*Ff + 255)/256, 256>>>(x, pos, W_es, b_es, W_ev);   // #3

    // layer 0 k_msg_mma is launch #4 -> ncu -s 5 -c 1 captures it
    k_msg_mma<<<296, 256, TC_SMEM>>>(W1, b1, W2, b2);                // #4
    k_invden<<<(Nn + 255)/256, 256>>>();                             // #5
    k_update<<<Nn/4, 128>>>(Ws, Wv);                                 // #6

    for (int l = 1; l < NLc; l++) {
        k_msg_mma<<<296, 256, TC_SMEM>>>(W1 + l*5*Hc, b1 + l*Hc,
                                         W2 + l*Hc*3*Ff, b2 + l*3*Ff);
        k_update<<<Nn/4, 128>>>(Ws + l*Ff*Ff, Wv + l*Ff*Ff);
    }

    k_gcnt<<<(Nn + 255)/256, 256>>>(batch);
    k_inv<<<1024, 128>>>(W_inv, b_inv, batch);
    k_pool_bn1<<<NINVc, 256>>>();
    k_fc1<<<Gc, 128>>>(g1, be1, Wf1, bf1);
    k_bn2<<<NINVc, 256>>>();
    k_head<<<Gc/4, 128>>>(g2, be2, Wf2, bf2, out);
}